// round 11
// baseline (speedup 1.0000x reference)
#include <cuda_runtime.h>
#include <cstdint>

// BoundarySeg: out[b,j,0:768]   = sum_{d=0..5} w[b,j,d] * hidden[b, min(j+d,L-1), :]
//              out[b,j,768:1536]= hidden[b,j,:] * sum_d w[b,j,d]
// w[b,j,d] = span_adjacency[b, j, j+d] if j+d < L else 0.
// B=16, L=1024, H=768. fp32.
//
// R11: steer L2 residency. Across graph replays the 96MB output stream was
// being pushed to DRAM every replay because the 48MB hidden tensor occupied
// L2. Now: hidden TMA loads carry L2::evict_first (transient, re-read from
// DRAM at 63MB/replay), output stores are default write-back so the 96MB
// output stays dirty-resident in L2 and is rewritten in place. DRAM bytes
// per replay drop ~93MB -> ~65-75MB.
// Skeleton = R9 (TJ=16 TMA-in + smem sliding window + direct STG).

#define BB 16
#define LL 1024
#define HH 768
#define HV (HH / 4)            // 192 float4 per row
#define TJ 16                  // j's per CTA
#define SPAN 6
#define NROWS (TJ + SPAN - 1)  // 21 rows staged

struct __align__(16) SmemLayout {
    float4   in[NROWS * HV];     // 64512 B
    float    w[TJ * SPAN];       // 384 B
    uint64_t mbar;
};

__device__ __forceinline__ uint32_t smem_u32(const void* p) {
    uint32_t a;
    asm("{ .reg .u64 t; cvta.to.shared.u64 t, %1; cvt.u32.u64 %0, t; }"
        : "=r"(a) : "l"(p));
    return a;
}

__global__ __launch_bounds__(HV)
void boundary_seg_kernel(const float* __restrict__ adj,
                         const float* __restrict__ hid,
                         float* __restrict__ out)
{
    extern __shared__ __align__(16) char smem_raw[];
    SmemLayout* sm = reinterpret_cast<SmemLayout*>(smem_raw);

    const int tile = blockIdx.x;           // b * 64 + jt
    const int b  = tile >> 6;
    const int j0 = (tile & 63) * TJ;
    const int t  = threadIdx.x;            // float4 column of H

    const int rl = min(NROWS, LL - j0);    // rows actually available
    const uint32_t in_bytes = (uint32_t)rl * HH * 4u;

    const uint32_t s_in   = smem_u32(sm->in);
    const uint32_t s_mbar = smem_u32(&sm->mbar);

    if (t == 0) {
        asm volatile("mbarrier.init.shared::cta.b64 [%0], %1;"
                     :: "r"(s_mbar), "r"(1) : "memory");
    }
    __syncthreads();

    if (t == 0) {
        asm volatile("mbarrier.arrive.expect_tx.shared::cta.b64 _, [%0], %1;"
                     :: "r"(s_mbar), "r"(in_bytes) : "memory");
        const float* src = hid + ((size_t)b * LL + j0) * HH;
        // Transient read: do NOT let the hidden tensor occupy L2 — the
        // output stream needs that capacity to stay dirty-resident.
        uint64_t pol;
        asm volatile("createpolicy.fractional.L2::evict_first.b64 %0, 1.0;"
                     : "=l"(pol));
        asm volatile(
            "cp.async.bulk.shared::cluster.global.mbarrier::complete_tx::bytes"
            ".L2::cache_hint [%0], [%1], %2, [%3], %4;"
            :: "r"(s_in), "l"(src), "r"(in_bytes), "r"(s_mbar), "l"(pol)
            : "memory");
    }

    // Weights: 96 scattered loads (2MB diagonal band, cheap to keep in L2).
    if (t < TJ * SPAN) {
        const int jj = t / SPAN;
        const int d  = t - jj * SPAN;
        const int col = j0 + jj + d;
        float w = 0.0f;
        if (col < LL)
            w = __ldg(adj + ((size_t)b * LL + (j0 + jj)) * LL + col);
        sm->w[jj * SPAN + d] = w;
    }
    __syncthreads();

    // Wait for the TMA bulk copy.
    {
        uint32_t done;
        do {
            asm volatile(
                "{ .reg .pred p;\n\t"
                "  mbarrier.try_wait.parity.shared::cta.b64 p, [%1], %2, 10000000;\n\t"
                "  selp.b32 %0, 1, 0, p; }"
                : "=r"(done) : "r"(s_mbar), "r"(0u) : "memory");
        } while (!done);
    }

    const int rmax = rl - 1;

    // Sliding register window of 6 rows (this thread's float4 column).
    float4 v[SPAN];
#pragma unroll
    for (int d = 0; d < SPAN; d++)
        v[d] = sm->in[min(d, rmax) * HV + t];

    float4* __restrict__ out4 = reinterpret_cast<float4*>(out);

#pragma unroll
    for (int jj = 0; jj < TJ; jj++) {
        const float w0 = sm->w[jj * SPAN + 0], w1 = sm->w[jj * SPAN + 1];
        const float w2 = sm->w[jj * SPAN + 2], w3 = sm->w[jj * SPAN + 3];
        const float w4 = sm->w[jj * SPAN + 4], w5 = sm->w[jj * SPAN + 5];
        const float wsum = ((w0 + w1) + (w2 + w3)) + (w4 + w5);

        float4 f;
        f.x = w0 * v[0].x; f.y = w0 * v[0].y;
        f.z = w0 * v[0].z; f.w = w0 * v[0].w;
        f.x = fmaf(w1, v[1].x, f.x); f.y = fmaf(w1, v[1].y, f.y);
        f.z = fmaf(w1, v[1].z, f.z); f.w = fmaf(w1, v[1].w, f.w);
        f.x = fmaf(w2, v[2].x, f.x); f.y = fmaf(w2, v[2].y, f.y);
        f.z = fmaf(w2, v[2].z, f.z); f.w = fmaf(w2, v[2].w, f.w);
        f.x = fmaf(w3, v[3].x, f.x); f.y = fmaf(w3, v[3].y, f.y);
        f.z = fmaf(w3, v[3].z, f.z); f.w = fmaf(w3, v[3].w, f.w);
        f.x = fmaf(w4, v[4].x, f.x); f.y = fmaf(w4, v[4].y, f.y);
        f.z = fmaf(w4, v[4].z, f.z); f.w = fmaf(w4, v[4].w, f.w);
        f.x = fmaf(w5, v[5].x, f.x); f.y = fmaf(w5, v[5].y, f.y);
        f.z = fmaf(w5, v[5].z, f.z); f.w = fmaf(w5, v[5].w, f.w);

        float4 s;
        s.x = v[0].x * wsum; s.y = v[0].y * wsum;
        s.z = v[0].z * wsum; s.w = v[0].w * wsum;

        // Default write-back stores: allocate in L2 and STAY there across
        // graph replays (rewritten in place, minimal DRAM writeback).
        const size_t obase = ((size_t)b * LL + (j0 + jj)) * (size_t)(2 * HV);
        out4[obase + t]      = f;
        out4[obase + HV + t] = s;

        // Slide the window.
#pragma unroll
        for (int d = 0; d < SPAN - 1; d++) v[d] = v[d + 1];
        v[SPAN - 1] = sm->in[min(jj + SPAN, rmax) * HV + t];
    }
}

extern "C" void kernel_launch(void* const* d_in, const int* in_sizes, int n_in,
                              void* d_out, int out_size)
{
    const float* adj = (const float*)d_in[0];   // (B,L,L,1)
    const float* hid = (const float*)d_in[1];   // (B,L,H)
    float* out = (float*)d_out;                 // (B,L,2H)

    const int smem_bytes = (int)sizeof(SmemLayout);
    static bool attr_set = false;
    if (!attr_set) {
        cudaFuncSetAttribute(boundary_seg_kernel,
                             cudaFuncAttributeMaxDynamicSharedMemorySize,
                             smem_bytes);
        attr_set = true;
    }

    const int grid = BB * (LL / TJ);            // 1024 CTAs
    boundary_seg_kernel<<<grid, HV, smem_bytes>>>(adj, hid, out);
}

// round 12
// speedup vs baseline: 1.0156x; 1.0156x over previous
#include <cuda_runtime.h>
#include <cstdint>

// BoundarySeg: out[b,j,0:768]   = sum_{d=0..5} w[b,j,d] * hidden[b, min(j+d,L-1), :]
//              out[b,j,768:1536]= hidden[b,j,:] * sum_d w[b,j,d]
// w[b,j,d] = span_adjacency[b, j, j+d] if j+d < L else 0.
// B=16, L=1024, H=768. fp32.
//
// R12: single change vs R9 (best, 21.4us): output stores are
// st.global.wt.v4 (write-through, NO write-allocate). Theory: with
// allocating stores every output byte costs the LTS twice (store write +
// dirty-line eviction read). Write-through streams each line through L2 to
// DRAM once, cutting LTS traffic ~37% (255MB -> 160MB per replay).

#define BB 16
#define LL 1024
#define HH 768
#define HV (HH / 4)            // 192 float4 per row
#define TJ 16                  // j's per CTA
#define SPAN 6
#define NROWS (TJ + SPAN - 1)  // 21 rows staged

struct __align__(16) SmemLayout {
    float4   in[NROWS * HV];     // 64512 B
    float    w[TJ * SPAN];       // 384 B
    uint64_t mbar;
};

__device__ __forceinline__ uint32_t smem_u32(const void* p) {
    uint32_t a;
    asm("{ .reg .u64 t; cvta.to.shared.u64 t, %1; cvt.u32.u64 %0, t; }"
        : "=r"(a) : "l"(p));
    return a;
}

// Write-through store: no L2 write-allocate, no later eviction read.
__device__ __forceinline__ void stwt4(float4* p, float4 v) {
    asm volatile("st.global.wt.v4.f32 [%0], {%1,%2,%3,%4};"
                 :: "l"(p), "f"(v.x), "f"(v.y), "f"(v.z), "f"(v.w) : "memory");
}

__global__ __launch_bounds__(HV)
void boundary_seg_kernel(const float* __restrict__ adj,
                         const float* __restrict__ hid,
                         float* __restrict__ out)
{
    extern __shared__ __align__(16) char smem_raw[];
    SmemLayout* sm = reinterpret_cast<SmemLayout*>(smem_raw);

    const int tile = blockIdx.x;           // b * 64 + jt
    const int b  = tile >> 6;
    const int j0 = (tile & 63) * TJ;
    const int t  = threadIdx.x;            // float4 column of H

    const int rl = min(NROWS, LL - j0);    // rows actually available
    const uint32_t in_bytes = (uint32_t)rl * HH * 4u;

    const uint32_t s_in   = smem_u32(sm->in);
    const uint32_t s_mbar = smem_u32(&sm->mbar);

    if (t == 0) {
        asm volatile("mbarrier.init.shared::cta.b64 [%0], %1;"
                     :: "r"(s_mbar), "r"(1) : "memory");
    }
    __syncthreads();

    if (t == 0) {
        asm volatile("mbarrier.arrive.expect_tx.shared::cta.b64 _, [%0], %1;"
                     :: "r"(s_mbar), "r"(in_bytes) : "memory");
        const float* src = hid + ((size_t)b * LL + j0) * HH;
        asm volatile(
            "cp.async.bulk.shared::cluster.global.mbarrier::complete_tx::bytes "
            "[%0], [%1], %2, [%3];"
            :: "r"(s_in), "l"(src), "r"(in_bytes), "r"(s_mbar) : "memory");
    }

    // Weights: 96 scattered L2 loads, overlapped with the TMA.
    if (t < TJ * SPAN) {
        const int jj = t / SPAN;
        const int d  = t - jj * SPAN;
        const int col = j0 + jj + d;
        float w = 0.0f;
        if (col < LL)
            w = __ldg(adj + ((size_t)b * LL + (j0 + jj)) * LL + col);
        sm->w[jj * SPAN + d] = w;
    }
    __syncthreads();

    // Wait for the TMA bulk copy.
    {
        uint32_t done;
        do {
            asm volatile(
                "{ .reg .pred p;\n\t"
                "  mbarrier.try_wait.parity.shared::cta.b64 p, [%1], %2, 10000000;\n\t"
                "  selp.b32 %0, 1, 0, p; }"
                : "=r"(done) : "r"(s_mbar), "r"(0u) : "memory");
        } while (!done);
    }

    const int rmax = rl - 1;

    // Sliding register window of 6 rows (this thread's float4 column).
    float4 v[SPAN];
#pragma unroll
    for (int d = 0; d < SPAN; d++)
        v[d] = sm->in[min(d, rmax) * HV + t];

    float4* __restrict__ out4 = reinterpret_cast<float4*>(out);

#pragma unroll
    for (int jj = 0; jj < TJ; jj++) {
        const float w0 = sm->w[jj * SPAN + 0], w1 = sm->w[jj * SPAN + 1];
        const float w2 = sm->w[jj * SPAN + 2], w3 = sm->w[jj * SPAN + 3];
        const float w4 = sm->w[jj * SPAN + 4], w5 = sm->w[jj * SPAN + 5];
        const float wsum = ((w0 + w1) + (w2 + w3)) + (w4 + w5);

        float4 f;
        f.x = w0 * v[0].x; f.y = w0 * v[0].y;
        f.z = w0 * v[0].z; f.w = w0 * v[0].w;
        f.x = fmaf(w1, v[1].x, f.x); f.y = fmaf(w1, v[1].y, f.y);
        f.z = fmaf(w1, v[1].z, f.z); f.w = fmaf(w1, v[1].w, f.w);
        f.x = fmaf(w2, v[2].x, f.x); f.y = fmaf(w2, v[2].y, f.y);
        f.z = fmaf(w2, v[2].z, f.z); f.w = fmaf(w2, v[2].w, f.w);
        f.x = fmaf(w3, v[3].x, f.x); f.y = fmaf(w3, v[3].y, f.y);
        f.z = fmaf(w3, v[3].z, f.z); f.w = fmaf(w3, v[3].w, f.w);
        f.x = fmaf(w4, v[4].x, f.x); f.y = fmaf(w4, v[4].y, f.y);
        f.z = fmaf(w4, v[4].z, f.z); f.w = fmaf(w4, v[4].w, f.w);
        f.x = fmaf(w5, v[5].x, f.x); f.y = fmaf(w5, v[5].y, f.y);
        f.z = fmaf(w5, v[5].z, f.z); f.w = fmaf(w5, v[5].w, f.w);

        float4 s;
        s.x = v[0].x * wsum; s.y = v[0].y * wsum;
        s.z = v[0].z * wsum; s.w = v[0].w * wsum;

        const size_t obase = ((size_t)b * LL + (j0 + jj)) * (size_t)(2 * HV);
        stwt4(out4 + obase + t, f);
        stwt4(out4 + obase + HV + t, s);

        // Slide the window.
#pragma unroll
        for (int d = 0; d < SPAN - 1; d++) v[d] = v[d + 1];
        v[SPAN - 1] = sm->in[min(jj + SPAN, rmax) * HV + t];
    }
}

extern "C" void kernel_launch(void* const* d_in, const int* in_sizes, int n_in,
                              void* d_out, int out_size)
{
    const float* adj = (const float*)d_in[0];   // (B,L,L,1)
    const float* hid = (const float*)d_in[1];   // (B,L,H)
    float* out = (float*)d_out;                 // (B,L,2H)

    const int smem_bytes = (int)sizeof(SmemLayout);
    static bool attr_set = false;
    if (!attr_set) {
        cudaFuncSetAttribute(boundary_seg_kernel,
                             cudaFuncAttributeMaxDynamicSharedMemorySize,
                             smem_bytes);
        attr_set = true;
    }

    const int grid = BB * (LL / TJ);            // 1024 CTAs
    boundary_seg_kernel<<<grid, HV, smem_bytes>>>(adj, hid, out);
}

// round 13
// speedup vs baseline: 1.0755x; 1.0590x over previous
#include <cuda_runtime.h>
#include <cstdint>

// BoundarySeg: out[b,j,0:768]   = sum_{d=0..5} w[b,j,d] * hidden[b, min(j+d,L-1), :]
//              out[b,j,768:1536]= hidden[b,j,:] * sum_d w[b,j,d]
// w[b,j,d] = span_adjacency[b, j, j+d] if j+d < L else 0.
// B=16, L=1024, H=768. fp32.
//
// R13: established floor = 96MB output writes at ~4.4TB/s effective HBM
// write throughput (~21.4us). This round shaves the per-wave prologue
// bubble: the input TMA is split into two phases (rows 0-12 / rows 13-20)
// on separate mbarriers, so stores for j 0..7 begin while the second half
// is still streaming in. Otherwise identical to the best kernel
// (TJ=16 TMA-in + smem sliding window + streaming .cs STG.128).

#define BB 16
#define LL 1024
#define HH 768
#define HV (HH / 4)            // 192 float4 per row
#define TJ 16                  // j's per CTA
#define SPAN 6
#define NROWS (TJ + SPAN - 1)  // 21 rows staged
#define P0ROWS 13              // rows needed for j 0..7

struct __align__(16) SmemLayout {
    float4   in[NROWS * HV];     // 64512 B
    float    w[TJ * SPAN];       // 384 B
    uint64_t mbar[2];
};

__device__ __forceinline__ uint32_t smem_u32(const void* p) {
    uint32_t a;
    asm("{ .reg .u64 t; cvta.to.shared.u64 t, %1; cvt.u32.u64 %0, t; }"
        : "=r"(a) : "l"(p));
    return a;
}

__device__ __forceinline__ void stcs4(float4* p, float4 v) {
    asm volatile("st.global.cs.v4.f32 [%0], {%1,%2,%3,%4};"
                 :: "l"(p), "f"(v.x), "f"(v.y), "f"(v.z), "f"(v.w) : "memory");
}

__device__ __forceinline__ void mbar_wait(uint32_t s_mb) {
    uint32_t done;
    do {
        asm volatile(
            "{ .reg .pred p;\n\t"
            "  mbarrier.try_wait.parity.shared::cta.b64 p, [%1], %2, 10000000;\n\t"
            "  selp.b32 %0, 1, 0, p; }"
            : "=r"(done) : "r"(s_mb), "r"(0u) : "memory");
    } while (!done);
}

__global__ __launch_bounds__(HV)
void boundary_seg_kernel(const float* __restrict__ adj,
                         const float* __restrict__ hid,
                         float* __restrict__ out)
{
    extern __shared__ __align__(16) char smem_raw[];
    SmemLayout* sm = reinterpret_cast<SmemLayout*>(smem_raw);

    const int tile = blockIdx.x;           // b * 64 + jt
    const int b  = tile >> 6;
    const int j0 = (tile & 63) * TJ;
    const int t  = threadIdx.x;            // float4 column of H

    const int rl = min(NROWS, LL - j0);    // 21, or 16 on the last tile
    const int rows0 = P0ROWS;              // rl >= 16 always, so phase0 = 13
    const int rows1 = rl - P0ROWS;         // 8 (or 3 on the last tile)

    if (t == 0) {
        asm volatile("mbarrier.init.shared::cta.b64 [%0], %1;"
                     :: "r"(smem_u32(&sm->mbar[0])), "r"(1) : "memory");
        asm volatile("mbarrier.init.shared::cta.b64 [%0], %1;"
                     :: "r"(smem_u32(&sm->mbar[1])), "r"(1) : "memory");
    }
    __syncthreads();

    if (t == 0) {
        const float* src = hid + ((size_t)b * LL + j0) * HH;
        // Phase 0: rows 0..12 (enough for j 0..7).
        {
            const uint32_t nb = (uint32_t)rows0 * HH * 4u;
            const uint32_t mb = smem_u32(&sm->mbar[0]);
            asm volatile("mbarrier.arrive.expect_tx.shared::cta.b64 _, [%0], %1;"
                         :: "r"(mb), "r"(nb) : "memory");
            asm volatile(
                "cp.async.bulk.shared::cluster.global.mbarrier::complete_tx::bytes "
                "[%0], [%1], %2, [%3];"
                :: "r"(smem_u32(sm->in)), "l"(src), "r"(nb), "r"(mb) : "memory");
        }
        // Phase 1: rows 13..rl-1 (for j 8..15), overlaps phase-0 compute.
        {
            const uint32_t nb = (uint32_t)rows1 * HH * 4u;
            const uint32_t mb = smem_u32(&sm->mbar[1]);
            asm volatile("mbarrier.arrive.expect_tx.shared::cta.b64 _, [%0], %1;"
                         :: "r"(mb), "r"(nb) : "memory");
            asm volatile(
                "cp.async.bulk.shared::cluster.global.mbarrier::complete_tx::bytes "
                "[%0], [%1], %2, [%3];"
                :: "r"(smem_u32(sm->in + P0ROWS * HV)),
                   "l"(src + (size_t)P0ROWS * HH), "r"(nb), "r"(mb) : "memory");
        }
    }

    // Weights: 96 scattered L2 loads, overlapped with the TMAs.
    if (t < TJ * SPAN) {
        const int jj = t / SPAN;
        const int d  = t - jj * SPAN;
        const int col = j0 + jj + d;
        float w = 0.0f;
        if (col < LL)
            w = __ldg(adj + ((size_t)b * LL + (j0 + jj)) * LL + col);
        sm->w[jj * SPAN + d] = w;
    }
    __syncthreads();

    // Wait for phase 0 only; start computing/storing j 0..7 immediately.
    mbar_wait(smem_u32(&sm->mbar[0]));

    const int rmax = rl - 1;

    // Sliding register window of 6 rows (this thread's float4 column).
    float4 v[SPAN];
#pragma unroll
    for (int d = 0; d < SPAN; d++)
        v[d] = sm->in[d * HV + t];          // rows 0..5 < P0ROWS, in-bounds

    float4* __restrict__ out4 = reinterpret_cast<float4*>(out);

#pragma unroll
    for (int jj = 0; jj < TJ; jj++) {
        if (jj == 8) {
            // Rows >= 13 needed from here on.
            mbar_wait(smem_u32(&sm->mbar[1]));
        }

        const float w0 = sm->w[jj * SPAN + 0], w1 = sm->w[jj * SPAN + 1];
        const float w2 = sm->w[jj * SPAN + 2], w3 = sm->w[jj * SPAN + 3];
        const float w4 = sm->w[jj * SPAN + 4], w5 = sm->w[jj * SPAN + 5];
        const float wsum = ((w0 + w1) + (w2 + w3)) + (w4 + w5);

        float4 f;
        f.x = w0 * v[0].x; f.y = w0 * v[0].y;
        f.z = w0 * v[0].z; f.w = w0 * v[0].w;
        f.x = fmaf(w1, v[1].x, f.x); f.y = fmaf(w1, v[1].y, f.y);
        f.z = fmaf(w1, v[1].z, f.z); f.w = fmaf(w1, v[1].w, f.w);
        f.x = fmaf(w2, v[2].x, f.x); f.y = fmaf(w2, v[2].y, f.y);
        f.z = fmaf(w2, v[2].z, f.z); f.w = fmaf(w2, v[2].w, f.w);
        f.x = fmaf(w3, v[3].x, f.x); f.y = fmaf(w3, v[3].y, f.y);
        f.z = fmaf(w3, v[3].z, f.z); f.w = fmaf(w3, v[3].w, f.w);
        f.x = fmaf(w4, v[4].x, f.x); f.y = fmaf(w4, v[4].y, f.y);
        f.z = fmaf(w4, v[4].z, f.z); f.w = fmaf(w4, v[4].w, f.w);
        f.x = fmaf(w5, v[5].x, f.x); f.y = fmaf(w5, v[5].y, f.y);
        f.z = fmaf(w5, v[5].z, f.z); f.w = fmaf(w5, v[5].w, f.w);

        float4 s;
        s.x = v[0].x * wsum; s.y = v[0].y * wsum;
        s.z = v[0].z * wsum; s.w = v[0].w * wsum;

        const size_t obase = ((size_t)b * LL + (j0 + jj)) * (size_t)(2 * HV);
        stcs4(out4 + obase + t, f);
        stcs4(out4 + obase + HV + t, s);

        // Slide the window. Next row index: jj+6. For jj<=6 that's <13
        // (phase-0 data); for jj>=7 it may be phase-1 — but jj=7's slide
        // happens after the jj==8 wait only for reads at jj>=8... careful:
        // the slide for jj=7 loads row 13 BEFORE the jj==8 wait. Guard it.
#pragma unroll
        for (int d = 0; d < SPAN - 1; d++) v[d] = v[d + 1];
        if (jj + SPAN < P0ROWS) {
            v[SPAN - 1] = sm->in[(jj + SPAN) * HV + t];
        } else if (jj == P0ROWS - SPAN) {   // jj == 7: row 13 is phase-1
            mbar_wait(smem_u32(&sm->mbar[1]));   // idempotent after first pass
            v[SPAN - 1] = sm->in[min(jj + SPAN, rmax) * HV + t];
        } else {
            v[SPAN - 1] = sm->in[min(jj + SPAN, rmax) * HV + t];
        }
    }
}

extern "C" void kernel_launch(void* const* d_in, const int* in_sizes, int n_in,
                              void* d_out, int out_size)
{
    const float* adj = (const float*)d_in[0];   // (B,L,L,1)
    const float* hid = (const float*)d_in[1];   // (B,L,H)
    float* out = (float*)d_out;                 // (B,L,2H)

    const int smem_bytes = (int)sizeof(SmemLayout);
    static bool attr_set = false;
    if (!attr_set) {
        cudaFuncSetAttribute(boundary_seg_kernel,
                             cudaFuncAttributeMaxDynamicSharedMemorySize,
                             smem_bytes);
        attr_set = true;
    }

    const int grid = BB * (LL / TJ);            // 1024 CTAs
    boundary_seg_kernel<<<grid, HV, smem_bytes>>>(adj, hid, out);
}

// round 14
// speedup vs baseline: 1.0767x; 1.0012x over previous
#include <cuda_runtime.h>
#include <cstdint>

// BoundarySeg: out[b,j,0:768]   = sum_{d=0..5} w[b,j,d] * hidden[b, min(j+d,L-1), :]
//              out[b,j,768:1536]= hidden[b,j,:] * sum_d w[b,j,d]
// w[b,j,d] = span_adjacency[b, j, j+d] if j+d < L else 0.
// B=16, L=1024, H=768. fp32.
//
// R14: two-phase TMA-in (rows 0-12, then rows 13-20) with the wait hoisted
// OUT of the hot loop: two branch-free unrolled 8-j loops, one unconditional
// mbarrier wait between them, register window reloaded at loop-2 entry.
// First stores issue after only 38KB is in flight instead of 64KB.
// Everything else = proven best kernel (TJ=16, smem sliding window,
// streaming .cs STG.128). Floor model: 96MB writes @ ~4.4TB/s ~= 21.4us.

#define BB 16
#define LL 1024
#define HH 768
#define HV (HH / 4)            // 192 float4 per row
#define TJ 16                  // j's per CTA
#define HALF (TJ / 2)          // 8
#define SPAN 6
#define NROWS (TJ + SPAN - 1)  // 21 rows staged
#define P0ROWS 13              // rows for j 0..7

struct __align__(16) SmemLayout {
    float4   in[NROWS * HV];     // 64512 B
    float    w[TJ * SPAN];       // 384 B
    uint64_t mbar[2];
};

__device__ __forceinline__ uint32_t smem_u32(const void* p) {
    uint32_t a;
    asm("{ .reg .u64 t; cvta.to.shared.u64 t, %1; cvt.u32.u64 %0, t; }"
        : "=r"(a) : "l"(p));
    return a;
}

__device__ __forceinline__ void stcs4(float4* p, float4 v) {
    asm volatile("st.global.cs.v4.f32 [%0], {%1,%2,%3,%4};"
                 :: "l"(p), "f"(v.x), "f"(v.y), "f"(v.z), "f"(v.w) : "memory");
}

__device__ __forceinline__ void mbar_wait(uint32_t s_mb) {
    uint32_t done;
    do {
        asm volatile(
            "{ .reg .pred p;\n\t"
            "  mbarrier.try_wait.parity.shared::cta.b64 p, [%1], %2, 10000000;\n\t"
            "  selp.b32 %0, 1, 0, p; }"
            : "=r"(done) : "r"(s_mb), "r"(0u) : "memory");
    } while (!done);
}

// One j-step: weights from smem, 6-tap FMA over the register window,
// two streaming stores, window slide (next row index passed in).
__device__ __forceinline__ void do_j(const SmemLayout* sm, float4* v,
                                     float4* __restrict__ out4,
                                     int b, int j, int jj, int nextrow, int t)
{
    const float w0 = sm->w[jj * SPAN + 0], w1 = sm->w[jj * SPAN + 1];
    const float w2 = sm->w[jj * SPAN + 2], w3 = sm->w[jj * SPAN + 3];
    const float w4 = sm->w[jj * SPAN + 4], w5 = sm->w[jj * SPAN + 5];
    const float wsum = ((w0 + w1) + (w2 + w3)) + (w4 + w5);

    float4 f;
    f.x = w0 * v[0].x; f.y = w0 * v[0].y;
    f.z = w0 * v[0].z; f.w = w0 * v[0].w;
    f.x = fmaf(w1, v[1].x, f.x); f.y = fmaf(w1, v[1].y, f.y);
    f.z = fmaf(w1, v[1].z, f.z); f.w = fmaf(w1, v[1].w, f.w);
    f.x = fmaf(w2, v[2].x, f.x); f.y = fmaf(w2, v[2].y, f.y);
    f.z = fmaf(w2, v[2].z, f.z); f.w = fmaf(w2, v[2].w, f.w);
    f.x = fmaf(w3, v[3].x, f.x); f.y = fmaf(w3, v[3].y, f.y);
    f.z = fmaf(w3, v[3].z, f.z); f.w = fmaf(w3, v[3].w, f.w);
    f.x = fmaf(w4, v[4].x, f.x); f.y = fmaf(w4, v[4].y, f.y);
    f.z = fmaf(w4, v[4].z, f.z); f.w = fmaf(w4, v[4].w, f.w);
    f.x = fmaf(w5, v[5].x, f.x); f.y = fmaf(w5, v[5].y, f.y);
    f.z = fmaf(w5, v[5].z, f.z); f.w = fmaf(w5, v[5].w, f.w);

    float4 s;
    s.x = v[0].x * wsum; s.y = v[0].y * wsum;
    s.z = v[0].z * wsum; s.w = v[0].w * wsum;

    const size_t obase = ((size_t)b * LL + j) * (size_t)(2 * HV);
    stcs4(out4 + obase + t, f);
    stcs4(out4 + obase + HV + t, s);

#pragma unroll
    for (int d = 0; d < SPAN - 1; d++) v[d] = v[d + 1];
    v[SPAN - 1] = sm->in[nextrow * HV + t];
}

__global__ __launch_bounds__(HV)
void boundary_seg_kernel(const float* __restrict__ adj,
                         const float* __restrict__ hid,
                         float* __restrict__ out)
{
    extern __shared__ __align__(16) char smem_raw[];
    SmemLayout* sm = reinterpret_cast<SmemLayout*>(smem_raw);

    const int tile = blockIdx.x;           // b * 64 + jt
    const int b  = tile >> 6;
    const int j0 = (tile & 63) * TJ;
    const int t  = threadIdx.x;            // float4 column of H

    const int rl   = min(NROWS, LL - j0);  // 21 (16 on last tile of each b)
    const int rmax = rl - 1;

    if (t == 0) {
        asm volatile("mbarrier.init.shared::cta.b64 [%0], %1;"
                     :: "r"(smem_u32(&sm->mbar[0])), "r"(1) : "memory");
        asm volatile("mbarrier.init.shared::cta.b64 [%0], %1;"
                     :: "r"(smem_u32(&sm->mbar[1])), "r"(1) : "memory");
    }
    __syncthreads();

    if (t == 0) {
        const float* src = hid + ((size_t)b * LL + j0) * HH;
        // Phase 0: rows 0..12 (covers j 0..7).
        {
            const uint32_t nb = P0ROWS * HH * 4u;
            const uint32_t mb = smem_u32(&sm->mbar[0]);
            asm volatile("mbarrier.arrive.expect_tx.shared::cta.b64 _, [%0], %1;"
                         :: "r"(mb), "r"(nb) : "memory");
            asm volatile(
                "cp.async.bulk.shared::cluster.global.mbarrier::complete_tx::bytes "
                "[%0], [%1], %2, [%3];"
                :: "r"(smem_u32(sm->in)), "l"(src), "r"(nb), "r"(mb) : "memory");
        }
        // Phase 1: rows 13..rl-1 (covers j 8..15); overlaps loop 1.
        {
            const uint32_t nb = (uint32_t)(rl - P0ROWS) * HH * 4u;
            const uint32_t mb = smem_u32(&sm->mbar[1]);
            asm volatile("mbarrier.arrive.expect_tx.shared::cta.b64 _, [%0], %1;"
                         :: "r"(mb), "r"(nb) : "memory");
            asm volatile(
                "cp.async.bulk.shared::cluster.global.mbarrier::complete_tx::bytes "
                "[%0], [%1], %2, [%3];"
                :: "r"(smem_u32(sm->in + P0ROWS * HV)),
                   "l"(src + (size_t)P0ROWS * HH), "r"(nb), "r"(mb) : "memory");
        }
    }

    // Weights: 96 scattered L2 loads, overlapped with both TMAs.
    if (t < TJ * SPAN) {
        const int jj = t / SPAN;
        const int d  = t - jj * SPAN;
        const int col = j0 + jj + d;
        float w = 0.0f;
        if (col < LL)
            w = __ldg(adj + ((size_t)b * LL + (j0 + jj)) * LL + col);
        sm->w[jj * SPAN + d] = w;
    }
    __syncthreads();

    float4* __restrict__ out4 = reinterpret_cast<float4*>(out);

    // ── Loop 1: j 0..7 — needs only phase-0 rows (0..12). ──
    mbar_wait(smem_u32(&sm->mbar[0]));

    float4 v[SPAN];
#pragma unroll
    for (int d = 0; d < SPAN; d++)
        v[d] = sm->in[d * HV + t];               // rows 0..5

#pragma unroll
    for (int jj = 0; jj < HALF; jj++) {
        // next row = jj+6; for jj=7 that's 13 (phase-1) — clamp to 12, the
        // value is discarded (window reloaded at loop-2 entry).
        const int nr = min(jj + SPAN, P0ROWS - 1);
        do_j(sm, v, out4, b, j0 + jj, jj, nr, t);
    }

    // ── Loop 2: j 8..15 — needs phase-1 rows. ──
    mbar_wait(smem_u32(&sm->mbar[1]));

#pragma unroll
    for (int d = 0; d < SPAN; d++)
        v[d] = sm->in[min(HALF + d, rmax) * HV + t];   // rows 8..13

#pragma unroll
    for (int jj = HALF; jj < TJ; jj++) {
        const int nr = min(jj + SPAN, rmax);
        do_j(sm, v, out4, b, j0 + jj, jj, nr, t);
    }
}

extern "C" void kernel_launch(void* const* d_in, const int* in_sizes, int n_in,
                              void* d_out, int out_size)
{
    const float* adj = (const float*)d_in[0];   // (B,L,L,1)
    const float* hid = (const float*)d_in[1];   // (B,L,H)
    float* out = (float*)d_out;                 // (B,L,2H)

    const int smem_bytes = (int)sizeof(SmemLayout);
    static bool attr_set = false;
    if (!attr_set) {
        cudaFuncSetAttribute(boundary_seg_kernel,
                             cudaFuncAttributeMaxDynamicSharedMemorySize,
                             smem_bytes);
        attr_set = true;
    }

    const int grid = BB * (LL / TJ);            // 1024 CTAs
    boundary_seg_kernel<<<grid, HV, smem_bytes>>>(adj, hid, out);
}